// round 15
// baseline (speedup 1.0000x reference)
#include <cuda_runtime.h>
#include <cuda_fp16.h>
#include <cstdint>

#define NN 100000
#define DD 128
#define HSTR 272     // bytes per smem f16 tile row (17 x 16B -> LDSM conflict-free)
#define SM_B_BYTES (DD * HSTR)                // 34816
#define SM_A_BYTES (DD * HSTR)                // 34816
#define SM_TOTAL   (SM_B_BYTES + SM_A_BYTES)  // 69632

// Scratch (static device globals — allocation-free at runtime)
__device__ __align__(16) __half g_feath[NN * DD];  // 25.6 MB f16 features
__device__ __align__(16) __half g_aggh[NN * DD];   // 25.6 MB f16 edge-sum accumulator
__device__ float  g_deg[NN];                       // in-degree (float)
__device__ __half g_Wh[DD * DD];                   // W as f16, row-major [n][k]

__device__ __forceinline__ uint32_t packh(float hi, float lo) {
    uint32_t r;
    asm("cvt.rn.f16x2.f32 %0, %1, %2;" : "=r"(r) : "f"(hi), "f"(lo));
    return r;
}

// ---------------------------------------------------------------------------
// fconv: feature -> f16, 8 f32 per thread (R12-validated best).
// Blocks 0-31 also convert W -> f16.
// ---------------------------------------------------------------------------
__global__ void fconv_kernel(const float4* __restrict__ feature,
                             const float* __restrict__ W, int n8) {
    int i = blockIdx.x * blockDim.x + threadIdx.x;
    if (blockIdx.x < 32) {
        int p = blockIdx.x * 256 + threadIdx.x;   // f16x2 word index of W
        float2 w = *reinterpret_cast<const float2*>(W + p * 2);
        reinterpret_cast<uint32_t*>(g_Wh)[p] = packh(w.y, w.x);
    }
    if (i < n8) {
        float4 a = feature[2 * i];
        float4 b = feature[2 * i + 1];
        uint4 o;
        o.x = packh(a.y, a.x);
        o.y = packh(a.w, a.z);
        o.z = packh(b.y, b.x);
        o.w = packh(b.w, b.z);
        reinterpret_cast<uint4*>(g_feath)[i] = o;
    }
}

// ---------------------------------------------------------------------------
// Edge scatter in f16: 4 edges/warp, 8 lanes/edge, 2 x 16B per lane.
// red.global.add.noftz.v4.f16x2 halves traffic vs f32 (validated R11).
// Index dtype detected in-warp (odd words of int64 < 2^31 are all zero).
// ---------------------------------------------------------------------------
__global__ void scatter_kernel(const void* __restrict__ srcv,
                               const void* __restrict__ dstv, int nE) {
    int gid = blockIdx.x * blockDim.x + threadIdx.x;
    int warp = gid >> 5, lane = gid & 31;

    unsigned int probe = reinterpret_cast<const unsigned int*>(srcv)[2 * lane + 1];
    bool is64 = (__reduce_or_sync(0xFFFFFFFFu, probe) == 0u);

    int e = warp * 4 + (lane >> 3);
    if (e >= nE) return;
    int li = lane & 7;

    long long s, d;
    if (is64) {
        s = reinterpret_cast<const long long*>(srcv)[e];
        d = reinterpret_cast<const long long*>(dstv)[e];
    } else {
        s = reinterpret_cast<const int*>(srcv)[e];
        d = reinterpret_cast<const int*>(dstv)[e];
    }

    const uint4* fr = reinterpret_cast<const uint4*>(g_feath + (size_t)s * DD);
    uint4 v0 = fr[li];
    uint4 v1 = fr[li + 8];
    __half* base = g_aggh + (size_t)d * DD;
    asm volatile("red.global.add.noftz.v4.f16x2 [%0], {%1,%2,%3,%4};"
                 :: "l"(base + li * 8), "r"(v0.x), "r"(v0.y), "r"(v0.z), "r"(v0.w)
                 : "memory");
    asm volatile("red.global.add.noftz.v4.f16x2 [%0], {%1,%2,%3,%4};"
                 :: "l"(base + (li + 8) * 8), "r"(v1.x), "r"(v1.y), "r"(v1.z), "r"(v1.w)
                 : "memory");
    if (li == 0) atomicAdd(&g_deg[d], 1.0f);
}

// ---------------------------------------------------------------------------
// fp16 GEMM, f16-accumulator HMMA with f32 promotion every 32 K:
//   out[m] = (aggh[m] * inv_deg[m]) @ Wh^T + b
// Warp's 8 n-tiles processed in two groups of 4 to bound register pressure
// (f16 partials 16 regs + f32 shadows 32 regs per group). Tiles staged via
// cp.async into 272B-strided smem; fragments via ldmatrix.x4.
// ---------------------------------------------------------------------------
__device__ __forceinline__ uint32_t smem_u32(const void* p) {
    uint32_t a;
    asm("{ .reg .u64 t; cvta.to.shared.u64 t, %1; cvt.u32.u64 %0, t; }"
        : "=r"(a) : "l"(p));
    return a;
}
__device__ __forceinline__ void mma16816hh(uint32_t* c, uint32_t a0, uint32_t a1,
                                           uint32_t a2, uint32_t a3,
                                           uint32_t b0, uint32_t b1) {
    asm volatile(
        "mma.sync.aligned.m16n8k16.row.col.f16.f16.f16.f16 "
        "{%0,%1}, {%2,%3,%4,%5}, {%6,%7}, {%0,%1};"
        : "+r"(c[0]), "+r"(c[1])
        : "r"(a0), "r"(a1), "r"(a2), "r"(a3), "r"(b0), "r"(b1));
}
__device__ __forceinline__ void ldsm4(uint32_t& r0, uint32_t& r1,
                                      uint32_t& r2, uint32_t& r3, uint32_t a) {
    asm volatile("ldmatrix.sync.aligned.m8n8.x4.shared.b16 {%0,%1,%2,%3}, [%4];"
                 : "=r"(r0), "=r"(r1), "=r"(r2), "=r"(r3) : "r"(a));
}

__global__ __launch_bounds__(256, 2) void gcn_mma_kernel(
    const float* __restrict__ bias, float* __restrict__ out, int nrows) {
    extern __shared__ char smem[];
    char* Bs = smem;                 // f16 W tile, rows n, 272B stride
    char* As = smem + SM_B_BYTES;    // f16 A tile, rows m, 272B stride

    const int t = threadIdx.x, wid = t >> 5, lane = t & 31;
    const int g = lane >> 2, s = lane & 3;
    const int warpM = (wid & 3) * 32;             // 4 warps over M
    const int warpN = (wid >> 2) * 64;            // 2 warps over N
    const int row0 = blockIdx.x * 128;

    // ---- cp.async both tiles: 8 x 16B per thread per tile ----
    {
        const uint32_t ab = smem_u32(As), bb = smem_u32(Bs);
        #pragma unroll
        for (int i = 0; i < 8; i++) {
            int c = t + i * 256;                  // row = c>>4, part = c&15
            int row = c >> 4, part = c & 15;
            bool ok = (row0 + row) < nrows;
            const __half* ga = g_aggh + (size_t)(ok ? row0 + row : row0) * DD + part * 8;
            uint32_t da = ab + row * HSTR + part * 16;
            int sz = ok ? 16 : 0;
            asm volatile("cp.async.cg.shared.global [%0], [%1], 16, %2;"
                         :: "r"(da), "l"(ga), "r"(sz) : "memory");
            const __half* gw = g_Wh + row * DD + part * 8;
            uint32_t dw = bb + row * HSTR + part * 16;
            asm volatile("cp.async.cg.shared.global [%0], [%1], 16;"
                         :: "r"(dw), "l"(gw) : "memory");
        }
        asm volatile("cp.async.commit_group;" ::: "memory");
    }

    const int r0 = row0 + warpM + g;              // rows r0, +8, +16, +24
    bool pr[4];
    #pragma unroll
    for (int j = 0; j < 4; j++) pr[j] = (r0 + 8 * j) < nrows;
    float inv[4];
    #pragma unroll
    for (int j = 0; j < 4; j++) {
        float dg = pr[j] ? g_deg[r0 + 8 * j] : 0.f;
        inv[j] = (dg > 0.f) ? (1.f / dg) : 0.f;
    }

    asm volatile("cp.async.wait_group 0;" ::: "memory");
    __syncthreads();

    // ldmatrix lane pointers (layout validated R10-R14)
    const uint32_t a_lp = smem_u32(As) + (warpM + (lane & 15)) * HSTR
                        + ((lane >> 4) & 1) * 16;
    const uint32_t b_lp = smem_u32(Bs)
                        + (warpN + (lane & 7) + ((lane >> 4) & 1) * 8) * HSTR
                        + ((lane >> 3) & 1) * 16;

    #pragma unroll
    for (int grp = 0; grp < 2; grp++) {
        // f32 shadows + f16 partials for this group's 4 n-tiles x 2 m-tiles
        float    accf[4][2][4];
        uint32_t acch[4][2][2];
        #pragma unroll
        for (int L = 0; L < 4; L++)
            #pragma unroll
            for (int mt = 0; mt < 2; mt++) {
                acch[L][mt][0] = 0u; acch[L][mt][1] = 0u;
                #pragma unroll
                for (int c = 0; c < 4; c++) accf[L][mt][c] = 0.f;
            }

        #pragma unroll
        for (int ks = 0; ks < 8; ks++) {
            uint32_t A[2][4];
            ldsm4(A[0][0], A[0][1], A[0][2], A[0][3], a_lp + ks * 32);
            ldsm4(A[1][0], A[1][1], A[1][2], A[1][3], a_lp + 16 * HSTR + ks * 32);
            #pragma unroll
            for (int npg = 0; npg < 2; npg++) {
                const int np = grp * 2 + npg;
                uint32_t b0, b1, b2, b3;
                ldsm4(b0, b1, b2, b3, b_lp + np * (16 * HSTR) + ks * 32);
                mma16816hh(acch[npg * 2][0],     A[0][0], A[0][1], A[0][2], A[0][3], b0, b1);
                mma16816hh(acch[npg * 2][1],     A[1][0], A[1][1], A[1][2], A[1][3], b0, b1);
                mma16816hh(acch[npg * 2 + 1][0], A[0][0], A[0][1], A[0][2], A[0][3], b2, b3);
                mma16816hh(acch[npg * 2 + 1][1], A[1][0], A[1][1], A[1][2], A[1][3], b2, b3);
            }
            if (ks & 1) {   // promote to f32 every 32 K (2 chained f16 roundings)
                #pragma unroll
                for (int L = 0; L < 4; L++)
                    #pragma unroll
                    for (int mt = 0; mt < 2; mt++) {
                        __half2 h0 = *reinterpret_cast<__half2*>(&acch[L][mt][0]);
                        __half2 h1 = *reinterpret_cast<__half2*>(&acch[L][mt][1]);
                        accf[L][mt][0] += __low2float(h0);
                        accf[L][mt][1] += __high2float(h0);
                        accf[L][mt][2] += __low2float(h1);
                        accf[L][mt][3] += __high2float(h1);
                        acch[L][mt][0] = 0u; acch[L][mt][1] = 0u;
                    }
            }
        }

        // ---- Group epilogue: out[m][n] = acc * inv_deg[m] + bias[n] ----
        #pragma unroll
        for (int L = 0; L < 4; L++) {
            int n = warpN + grp * 32 + (L >> 1) * 16 + (L & 1) * 8 + 2 * s;
            float2 bv = *reinterpret_cast<const float2*>(&bias[n]);
            #pragma unroll
            for (int mt = 0; mt < 2; mt++) {
                int rA = r0 + mt * 16, rB = rA + 8;
                if (pr[mt * 2]) {
                    float2 o = make_float2(accf[L][mt][0] * inv[mt * 2] + bv.x,
                                           accf[L][mt][1] * inv[mt * 2] + bv.y);
                    *reinterpret_cast<float2*>(&out[(size_t)rA * DD + n]) = o;
                }
                if (pr[mt * 2 + 1]) {
                    float2 o = make_float2(accf[L][mt][2] * inv[mt * 2 + 1] + bv.x,
                                           accf[L][mt][3] * inv[mt * 2 + 1] + bv.y);
                    *reinterpret_cast<float2*>(&out[(size_t)rB * DD + n]) = o;
                }
            }
        }
    }
}

extern "C" void kernel_launch(void* const* d_in, const int* in_sizes, int n_in,
                              void* d_out, int out_size) {
    const float* feature = (const float*)d_in[0];   // [100000,128] f32
    const float* W       = (const float*)d_in[1];   // [128,128]   f32
    const float* bias    = (const float*)d_in[2];   // [128]       f32
    const void*  src     = d_in[3];                 // [625000] int64/int32
    const void*  dst     = d_in[4];                 // [625000] int64/int32
    float*       out     = (float*)d_out;           // [100000,128] f32

    const int nE = in_sizes[3];
    const int nN = in_sizes[0] / DD;

    // Zero scratch via graph memset nodes (no allocation; capture-legal).
    void* aggh_ptr = nullptr; void* deg_ptr = nullptr;
    cudaGetSymbolAddress(&aggh_ptr, g_aggh);
    cudaGetSymbolAddress(&deg_ptr, g_deg);
    cudaMemsetAsync(aggh_ptr, 0, sizeof(__half) * NN * DD, 0);
    cudaMemsetAsync(deg_ptr, 0, sizeof(float) * NN, 0);

    fconv_kernel<<<(NN * DD / 8 + 255) / 256, 256>>>(
        (const float4*)feature, W, NN * DD / 8);

    long long scatter_threads = (long long)nE * 8;   // 8 lanes per edge
    scatter_kernel<<<(unsigned)((scatter_threads + 255) / 256), 256>>>(
        src, dst, nE);

    cudaFuncSetAttribute(gcn_mma_kernel,
                         cudaFuncAttributeMaxDynamicSharedMemorySize, SM_TOTAL);
    gcn_mma_kernel<<<(nN + 127) / 128, 256, SM_TOTAL>>>(bias, out, nN);
}

// round 16
// speedup vs baseline: 1.0370x; 1.0370x over previous
#include <cuda_runtime.h>
#include <cuda_fp16.h>
#include <cstdint>

#define NN 100000
#define DD 128
#define HSTR 272     // bytes per smem f16 tile row (17 x 16B -> LDSM conflict-free)
#define SM_B_BYTES (DD * HSTR)                // 34816
#define SM_A_BYTES (DD * HSTR)                // 34816
#define SM_TOTAL   (SM_B_BYTES + SM_A_BYTES)  // 69632

// Scratch (static device globals — allocation-free at runtime)
__device__ __align__(16) __half g_feath[NN * DD];  // 25.6 MB f16 features
__device__ __align__(16) __half g_aggh[NN * DD];   // 25.6 MB f16 edge-sum accumulator
__device__ float  g_deg[NN];                       // in-degree (float)
__device__ __half g_Wh[DD * DD];                   // W as f16, row-major [n][k]

__device__ __forceinline__ uint32_t packh(float hi, float lo) {
    uint32_t r;
    asm("cvt.rn.f16x2.f32 %0, %1, %2;" : "=r"(r) : "f"(hi), "f"(lo));
    return r;
}

// ---------------------------------------------------------------------------
// fconv: feature -> f16, 8 f32 per thread (R12-validated best).
// Blocks 0-31 also convert W -> f16.
// ---------------------------------------------------------------------------
__global__ void fconv_kernel(const float4* __restrict__ feature,
                             const float* __restrict__ W, int n8) {
    int i = blockIdx.x * blockDim.x + threadIdx.x;
    if (blockIdx.x < 32) {
        int p = blockIdx.x * 256 + threadIdx.x;   // f16x2 word index of W
        float2 w = *reinterpret_cast<const float2*>(W + p * 2);
        reinterpret_cast<uint32_t*>(g_Wh)[p] = packh(w.y, w.x);
    }
    if (i < n8) {
        float4 a = feature[2 * i];
        float4 b = feature[2 * i + 1];
        uint4 o;
        o.x = packh(a.y, a.x);
        o.y = packh(a.w, a.z);
        o.z = packh(b.y, b.x);
        o.w = packh(b.w, b.z);
        reinterpret_cast<uint4*>(g_feath)[i] = o;
    }
}

// ---------------------------------------------------------------------------
// Edge scatter in f16: 4 edges/warp, 8 lanes/edge, 2 x 16B per lane.
// red.global.add.noftz.v4.f16x2 halves traffic vs f32 (validated R11).
// Index dtype detected in-warp (odd words of int64 < 2^31 are all zero).
// ---------------------------------------------------------------------------
__global__ void scatter_kernel(const void* __restrict__ srcv,
                               const void* __restrict__ dstv, int nE) {
    int gid = blockIdx.x * blockDim.x + threadIdx.x;
    int warp = gid >> 5, lane = gid & 31;

    unsigned int probe = reinterpret_cast<const unsigned int*>(srcv)[2 * lane + 1];
    bool is64 = (__reduce_or_sync(0xFFFFFFFFu, probe) == 0u);

    int e = warp * 4 + (lane >> 3);
    if (e >= nE) return;
    int li = lane & 7;

    long long s, d;
    if (is64) {
        s = reinterpret_cast<const long long*>(srcv)[e];
        d = reinterpret_cast<const long long*>(dstv)[e];
    } else {
        s = reinterpret_cast<const int*>(srcv)[e];
        d = reinterpret_cast<const int*>(dstv)[e];
    }

    const uint4* fr = reinterpret_cast<const uint4*>(g_feath + (size_t)s * DD);
    uint4 v0 = fr[li];
    uint4 v1 = fr[li + 8];
    __half* base = g_aggh + (size_t)d * DD;
    asm volatile("red.global.add.noftz.v4.f16x2 [%0], {%1,%2,%3,%4};"
                 :: "l"(base + li * 8), "r"(v0.x), "r"(v0.y), "r"(v0.z), "r"(v0.w)
                 : "memory");
    asm volatile("red.global.add.noftz.v4.f16x2 [%0], {%1,%2,%3,%4};"
                 :: "l"(base + (li + 8) * 8), "r"(v1.x), "r"(v1.y), "r"(v1.z), "r"(v1.w)
                 : "memory");
    if (li == 0) atomicAdd(&g_deg[d], 1.0f);
}

// ---------------------------------------------------------------------------
// fp16 GEMM via mma.sync.m16n8k16 (R13-validated best GEMM config):
//   out[m] = (aggh[m] * inv_deg[m]) @ Wh^T + b
// Bound by legacy HMMA issue rate (~rt 12-16 cyc/SMSP) — at its floor.
// ---------------------------------------------------------------------------
__device__ __forceinline__ uint32_t smem_u32(const void* p) {
    uint32_t a;
    asm("{ .reg .u64 t; cvta.to.shared.u64 t, %1; cvt.u32.u64 %0, t; }"
        : "=r"(a) : "l"(p));
    return a;
}
__device__ __forceinline__ void mma16816h(float* c, uint32_t a0, uint32_t a1,
                                          uint32_t a2, uint32_t a3,
                                          uint32_t b0, uint32_t b1) {
    asm volatile(
        "mma.sync.aligned.m16n8k16.row.col.f32.f16.f16.f32 "
        "{%0,%1,%2,%3}, {%4,%5,%6,%7}, {%8,%9}, {%0,%1,%2,%3};"
        : "+f"(c[0]), "+f"(c[1]), "+f"(c[2]), "+f"(c[3])
        : "r"(a0), "r"(a1), "r"(a2), "r"(a3), "r"(b0), "r"(b1));
}
__device__ __forceinline__ void ldsm4(uint32_t& r0, uint32_t& r1,
                                      uint32_t& r2, uint32_t& r3, uint32_t a) {
    asm volatile("ldmatrix.sync.aligned.m8n8.x4.shared.b16 {%0,%1,%2,%3}, [%4];"
                 : "=r"(r0), "=r"(r1), "=r"(r2), "=r"(r3) : "r"(a));
}

__global__ __launch_bounds__(256, 2) void gcn_mma_kernel(
    const float* __restrict__ bias, float* __restrict__ out, int nrows) {
    extern __shared__ char smem[];
    char* Bs = smem;                 // f16 W tile, rows n, 272B stride
    char* As = smem + SM_B_BYTES;    // f16 A tile, rows m, 272B stride

    const int t = threadIdx.x, wid = t >> 5, lane = t & 31;
    const int g = lane >> 2, s = lane & 3;
    const int warpM = (wid & 3) * 32;             // 4 warps over M
    const int warpN = (wid >> 2) * 64;            // 2 warps over N
    const int row0 = blockIdx.x * 128;

    // ---- cp.async both tiles: 8 x 16B per thread per tile ----
    {
        const uint32_t ab = smem_u32(As), bb = smem_u32(Bs);
        #pragma unroll
        for (int i = 0; i < 8; i++) {
            int c = t + i * 256;                  // row = c>>4, part = c&15
            int row = c >> 4, part = c & 15;
            bool ok = (row0 + row) < nrows;
            const __half* ga = g_aggh + (size_t)(ok ? row0 + row : row0) * DD + part * 8;
            uint32_t da = ab + row * HSTR + part * 16;
            int sz = ok ? 16 : 0;
            asm volatile("cp.async.cg.shared.global [%0], [%1], 16, %2;"
                         :: "r"(da), "l"(ga), "r"(sz) : "memory");
            const __half* gw = g_Wh + row * DD + part * 8;
            uint32_t dw = bb + row * HSTR + part * 16;
            asm volatile("cp.async.cg.shared.global [%0], [%1], 16;"
                         :: "r"(dw), "l"(gw) : "memory");
        }
        asm volatile("cp.async.commit_group;" ::: "memory");
    }

    const int r0 = row0 + warpM + g;              // rows r0, +8, +16, +24
    bool pr[4];
    #pragma unroll
    for (int j = 0; j < 4; j++) pr[j] = (r0 + 8 * j) < nrows;

    float acc[2][8][4];
    #pragma unroll
    for (int mt = 0; mt < 2; mt++)
        #pragma unroll
        for (int nt = 0; nt < 8; nt++)
            #pragma unroll
            for (int c = 0; c < 4; c++) acc[mt][nt][c] = 0.f;

    asm volatile("cp.async.wait_group 0;" ::: "memory");
    __syncthreads();

    // ldmatrix lane pointers (layout validated R10-R15)
    const uint32_t a_lp = smem_u32(As) + (warpM + (lane & 15)) * HSTR
                        + ((lane >> 4) & 1) * 16;
    const uint32_t b_lp = smem_u32(Bs)
                        + (warpN + (lane & 7) + ((lane >> 4) & 1) * 8) * HSTR
                        + ((lane >> 3) & 1) * 16;

    #pragma unroll
    for (int ks = 0; ks < 8; ks++) {
        uint32_t A[2][4];
        ldsm4(A[0][0], A[0][1], A[0][2], A[0][3], a_lp + ks * 32);
        ldsm4(A[1][0], A[1][1], A[1][2], A[1][3], a_lp + 16 * HSTR + ks * 32);
        #pragma unroll
        for (int np = 0; np < 4; np++) {
            uint32_t b0, b1, b2, b3;
            ldsm4(b0, b1, b2, b3, b_lp + np * (16 * HSTR) + ks * 32);
            mma16816h(acc[0][np * 2],     A[0][0], A[0][1], A[0][2], A[0][3], b0, b1);
            mma16816h(acc[1][np * 2],     A[1][0], A[1][1], A[1][2], A[1][3], b0, b1);
            mma16816h(acc[0][np * 2 + 1], A[0][0], A[0][1], A[0][2], A[0][3], b2, b3);
            mma16816h(acc[1][np * 2 + 1], A[1][0], A[1][1], A[1][2], A[1][3], b2, b3);
        }
    }

    // ---- Epilogue: out[m][n] = acc * inv_deg[m] + bias[n] ----
    float inv[4];
    #pragma unroll
    for (int j = 0; j < 4; j++) {
        float dg = pr[j] ? g_deg[r0 + 8 * j] : 0.f;
        inv[j] = (dg > 0.f) ? (1.f / dg) : 0.f;
    }
    #pragma unroll
    for (int mt = 0; mt < 2; mt++) {
        #pragma unroll
        for (int nt = 0; nt < 8; nt++) {
            int n = warpN + nt * 8 + 2 * s;
            float2 bv = *reinterpret_cast<const float2*>(&bias[n]);
            int rA = r0 + mt * 16, rB = rA + 8;
            if (pr[mt * 2]) {
                float2 o = make_float2(acc[mt][nt][0] * inv[mt * 2] + bv.x,
                                       acc[mt][nt][1] * inv[mt * 2] + bv.y);
                *reinterpret_cast<float2*>(&out[(size_t)rA * DD + n]) = o;
            }
            if (pr[mt * 2 + 1]) {
                float2 o = make_float2(acc[mt][nt][2] * inv[mt * 2 + 1] + bv.x,
                                       acc[mt][nt][3] * inv[mt * 2 + 1] + bv.y);
                *reinterpret_cast<float2*>(&out[(size_t)rB * DD + n]) = o;
            }
        }
    }
}

extern "C" void kernel_launch(void* const* d_in, const int* in_sizes, int n_in,
                              void* d_out, int out_size) {
    const float* feature = (const float*)d_in[0];   // [100000,128] f32
    const float* W       = (const float*)d_in[1];   // [128,128]   f32
    const float* bias    = (const float*)d_in[2];   // [128]       f32
    const void*  src     = d_in[3];                 // [625000] int64/int32
    const void*  dst     = d_in[4];                 // [625000] int64/int32
    float*       out     = (float*)d_out;           // [100000,128] f32

    const int nE = in_sizes[3];
    const int nN = in_sizes[0] / DD;

    // One-time host-side resources (no device memory; identical work per call).
    static cudaStream_t s_aux = nullptr;
    static cudaEvent_t  ev_fork = nullptr, ev_join = nullptr;
    if (s_aux == nullptr) {
        cudaStreamCreateWithFlags(&s_aux, cudaStreamNonBlocking);
        cudaEventCreateWithFlags(&ev_fork, cudaEventDisableTiming);
        cudaEventCreateWithFlags(&ev_join, cudaEventDisableTiming);
    }

    void* aggh_ptr = nullptr; void* deg_ptr = nullptr;
    cudaGetSymbolAddress(&aggh_ptr, g_aggh);
    cudaGetSymbolAddress(&deg_ptr, g_deg);

    // Fork: memsets (needed only by scatter) run parallel with fconv.
    cudaEventRecord(ev_fork, 0);
    cudaStreamWaitEvent(s_aux, ev_fork, 0);
    cudaMemsetAsync(aggh_ptr, 0, sizeof(__half) * NN * DD, s_aux);
    cudaMemsetAsync(deg_ptr, 0, sizeof(float) * NN, s_aux);
    cudaEventRecord(ev_join, s_aux);

    fconv_kernel<<<(NN * DD / 8 + 255) / 256, 256>>>(
        (const float4*)feature, W, NN * DD / 8);

    // Join before scatter (needs both fconv output and zeroed accumulators).
    cudaStreamWaitEvent(0, ev_join, 0);

    long long scatter_threads = (long long)nE * 8;   // 8 lanes per edge
    scatter_kernel<<<(unsigned)((scatter_threads + 255) / 256), 256>>>(
        src, dst, nE);

    cudaFuncSetAttribute(gcn_mma_kernel,
                         cudaFuncAttributeMaxDynamicSharedMemorySize, SM_TOTAL);
    gcn_mma_kernel<<<(nN + 127) / 128, 256, SM_TOTAL>>>(bias, out, nN);
}